// round 5
// baseline (speedup 1.0000x reference)
#include <cuda_runtime.h>
#include <cuda_bf16.h>
#include <cstdint>
#include <math.h>

#define NCLU 8
#define DIN  1024
#define DHID 256
#define NTOK 65536
#define RPB  128            // rows per CTA
#define KT   32             // k per tile
#define NKT  (DIN / KT)     // 32 tiles
#define APAD 40             // padded bf16 stride (80 B) -> conflict-free frag loads

// ------------- device scratch (no allocs allowed) -------------
__device__ __nv_bfloat16 g_w1b[DHID * DIN];
__device__ float         g_segsum[NCLU * DHID];
__device__ unsigned int  g_counts[NCLU];

// ---------------------------------------------------------------
// Kernel 1: convert W1 to bf16, zero accumulators (runs every launch)
// ---------------------------------------------------------------
__global__ void prep_kernel(const float* __restrict__ W1) {
    int i = blockIdx.x * blockDim.x + threadIdx.x;   // 512*512 = 262144 exactly
    g_w1b[i] = __float2bfloat16(W1[i]);
    if (i < NCLU * DHID) g_segsum[i] = 0.f;
    if (i < NCLU)        g_counts[i] = 0u;
}

// ---------------------------------------------------------------
// Kernel 2: fused GEMM + bias + ReLU + per-cluster segment sum
//   grid 512, block 512 (16 warps, 4x4 warp grid, warp tile 32x64)
// ---------------------------------------------------------------
__device__ __forceinline__ uint32_t pack2(float a, float b) {
    __nv_bfloat162 h = __floats2bfloat162_rn(a, b);
    return *reinterpret_cast<const uint32_t*>(&h);
}

__device__ __forceinline__ void mma16816(float c[4], const uint32_t a[4],
                                         uint32_t b0, uint32_t b1) {
    asm volatile(
        "mma.sync.aligned.m16n8k16.row.col.f32.bf16.bf16.f32 "
        "{%0,%1,%2,%3}, {%4,%5,%6,%7}, {%8,%9}, {%0,%1,%2,%3};"
        : "+f"(c[0]), "+f"(c[1]), "+f"(c[2]), "+f"(c[3])
        : "r"(a[0]), "r"(a[1]), "r"(a[2]), "r"(a[3]), "r"(b0), "r"(b1));
}

__global__ void __launch_bounds__(512, 1)
main_kernel(const float* __restrict__ x,
            const int*   __restrict__ cid_g,
            const float* __restrict__ b1_g) {
    __shared__ __align__(16) __nv_bfloat16 As[RPB][APAD];    // 10240 B
    __shared__ __align__(16) __nv_bfloat16 Bs[DHID][APAD];   // 20480 B
    __shared__ float accS[NCLU][DHID];                       // 8192 B
    __shared__ float b1s[DHID];
    __shared__ int   cids[RPB];
    __shared__ unsigned int histS[NCLU];

    const int tid   = threadIdx.x;
    const int lane  = tid & 31;
    const int wid   = tid >> 5;
    const int mBase = (wid >> 2) * 32;       // warp row block
    const int nBase = (wid & 3) * 64;        // warp col block
    const int rowBase = blockIdx.x * RPB;

    // ---- phase 0: zero shared accumulators, preload bias & cluster ids ----
    for (int i = tid; i < NCLU * DHID; i += 512) (&accS[0][0])[i] = 0.f;
    if (tid < NCLU) histS[tid] = 0u;
    if (tid < DHID) b1s[tid] = b1_g[tid];
    __syncthreads();
    if (tid < RPB) {
        int c = cid_g[rowBase + tid];
        cids[tid] = c;
        atomicAdd(&histS[c], 1u);
    }

    // ---- global load helpers (2 A tasks + 2 B tasks per thread) ----
    // A task t in [0,1024): r = t>>3, f4 = t&7  (float4 of x)
    // B task t in [0,1024): h = t>>2, q  = t&3  (uint4 = 8 bf16 of W1)
    const int ar0 = tid >> 3,        af0 = tid & 7;
    const int ar1 = (tid + 512) >> 3, af1 = (tid + 512) & 7;
    const int bh0 = tid >> 2,        bq0 = tid & 3;
    const int bh1 = (tid + 512) >> 2, bq1 = (tid + 512) & 3;

    float4 aF0, aF1;
    uint4  bF0, bF1;

    auto ldg_tile = [&](int t) {
        int k0 = t * KT;
        aF0 = *reinterpret_cast<const float4*>(
            x + (size_t)(rowBase + ar0) * DIN + k0 + af0 * 4);
        aF1 = *reinterpret_cast<const float4*>(
            x + (size_t)(rowBase + ar1) * DIN + k0 + af1 * 4);
        bF0 = *reinterpret_cast<const uint4*>(
            g_w1b + (size_t)bh0 * DIN + k0 + bq0 * 8);
        bF1 = *reinterpret_cast<const uint4*>(
            g_w1b + (size_t)bh1 * DIN + k0 + bq1 * 8);
    };
    auto sts_tile = [&]() {
        uint32_t* pa0 = reinterpret_cast<uint32_t*>(&As[ar0][af0 * 4]);
        pa0[0] = pack2(aF0.x, aF0.y);  pa0[1] = pack2(aF0.z, aF0.w);
        uint32_t* pa1 = reinterpret_cast<uint32_t*>(&As[ar1][af1 * 4]);
        pa1[0] = pack2(aF1.x, aF1.y);  pa1[1] = pack2(aF1.z, aF1.w);
        *reinterpret_cast<uint4*>(&Bs[bh0][bq0 * 8]) = bF0;
        *reinterpret_cast<uint4*>(&Bs[bh1][bq1 * 8]) = bF1;
    };

    float acc[2][8][4];
#pragma unroll
    for (int m = 0; m < 2; ++m)
#pragma unroll
        for (int n = 0; n < 8; ++n)
#pragma unroll
            for (int q = 0; q < 4; ++q) acc[m][n][q] = 0.f;

    const int fr  = lane >> 2;           // 0..7
    const int fc2 = (lane & 3) << 1;     // 0,2,4,6

    // ---- mainloop: single SMEM buffer + register prefetch of next tile ----
    ldg_tile(0);
    for (int t = 0; t < NKT; ++t) {
        __syncthreads();                 // previous compute done -> safe to overwrite
        sts_tile();
        if (t + 1 < NKT) ldg_tile(t + 1);   // overlaps with compute below
        __syncthreads();

#pragma unroll
        for (int ks = 0; ks < 2; ++ks) {
            const int kb = ks * 16;
            uint32_t a[2][4];
#pragma unroll
            for (int m = 0; m < 2; ++m) {
                const int r = mBase + m * 16 + fr;
                const int c = fc2 + kb;
                a[m][0] = *reinterpret_cast<const uint32_t*>(&As[r][c]);
                a[m][1] = *reinterpret_cast<const uint32_t*>(&As[r + 8][c]);
                a[m][2] = *reinterpret_cast<const uint32_t*>(&As[r][c + 8]);
                a[m][3] = *reinterpret_cast<const uint32_t*>(&As[r + 8][c + 8]);
            }
#pragma unroll
            for (int n = 0; n < 8; ++n) {
                const int col = nBase + n * 8 + fr;
                const int kk  = fc2 + kb;
                uint32_t b0 = *reinterpret_cast<const uint32_t*>(&Bs[col][kk]);
                uint32_t b1 = *reinterpret_cast<const uint32_t*>(&Bs[col][kk + 8]);
                mma16816(acc[0][n], a[0], b0, b1);
                mma16816(acc[1][n], a[1], b0, b1);
            }
        }
    }

    // ---- epilogue: bias + ReLU + per-cluster accumulation ----
#pragma unroll
    for (int m = 0; m < 2; ++m) {
        const int r    = mBase + m * 16 + fr;
        const int cid0 = cids[r];
        const int cid1 = cids[r + 8];
#pragma unroll
        for (int n = 0; n < 8; ++n) {
            const int col = nBase + n * 8 + fc2;
            const float bia0 = b1s[col], bia1 = b1s[col + 1];
            float v00 = fmaxf(acc[m][n][0] + bia0, 0.f);
            float v01 = fmaxf(acc[m][n][1] + bia1, 0.f);
            float v10 = fmaxf(acc[m][n][2] + bia0, 0.f);
            float v11 = fmaxf(acc[m][n][3] + bia1, 0.f);
            atomicAdd(&accS[cid0][col],     v00);
            atomicAdd(&accS[cid0][col + 1], v01);
            atomicAdd(&accS[cid1][col],     v10);
            atomicAdd(&accS[cid1][col + 1], v11);
        }
    }
    __syncthreads();

    for (int i = tid; i < NCLU * DHID; i += 512)
        atomicAdd(&g_segsum[i], (&accS[0][0])[i]);
    if (tid < NCLU) atomicAdd(&g_counts[tid], histS[tid]);
}

// ---------------------------------------------------------------
// Kernel 3: cluster means + gated attention + softmax + combine
//   1 block, 256 threads (thread j owns hidden index j)
// ---------------------------------------------------------------
__global__ void __launch_bounds__(256, 1)
finalize_kernel(const float* __restrict__ Wf, const float* __restrict__ bf,
                const float* __restrict__ Wa, const float* __restrict__ ba,
                const float* __restrict__ Wb, const float* __restrict__ bb,
                const float* __restrict__ Wc, const float* __restrict__ bc,
                float* __restrict__ out) {
    __shared__ float hc[NCLU][DHID];
    __shared__ float hp[NCLU][DHID];
    __shared__ float ag[NCLU][DHID];
    __shared__ float prob[NCLU];

    const int j = threadIdx.x;

    // cluster means (empty cluster -> 0)
#pragma unroll
    for (int k = 0; k < NCLU; ++k) {
        float cnt = fmaxf((float)g_counts[k], 1.0f);
        hc[k][j] = g_segsum[k * DHID + j] / cnt;
    }
    __syncthreads();

    // h_path = relu(hc @ Wf^T + bf)
    {
        float acc[NCLU];
        float bias = bf[j];
#pragma unroll
        for (int k = 0; k < NCLU; ++k) acc[k] = bias;
#pragma unroll 4
        for (int d = 0; d < DHID; ++d) {
            float w = Wf[j * DHID + d];
#pragma unroll
            for (int k = 0; k < NCLU; ++k) acc[k] += w * hc[k][d];
        }
#pragma unroll
        for (int k = 0; k < NCLU; ++k) hp[k][j] = fmaxf(acc[k], 0.f);
    }
    __syncthreads();

    // gated attention: a = tanh(hp@Wa^T+ba), g = sigmoid(hp@Wb^T+bb)
    {
        float accA[NCLU], accB[NCLU];
        float biasA = ba[j], biasB = bb[j];
#pragma unroll
        for (int k = 0; k < NCLU; ++k) { accA[k] = biasA; accB[k] = biasB; }
#pragma unroll 4
        for (int d = 0; d < DHID; ++d) {
            float wa = Wa[j * DHID + d];
            float wb = Wb[j * DHID + d];
#pragma unroll
            for (int k = 0; k < NCLU; ++k) {
                float h = hp[k][d];
                accA[k] += wa * h;
                accB[k] += wb * h;
            }
        }
#pragma unroll
        for (int k = 0; k < NCLU; ++k) {
            float a = tanhf(accA[k]);
            float g = 1.0f / (1.0f + expf(-accB[k]));
            ag[k][j] = a * g;
        }
    }
    __syncthreads();

    // scores s_k = Wc . ag[k] + bc ; softmax over 8 (thread 0)
    if (j < NCLU) {
        float s = bc[0];
#pragma unroll 4
        for (int d = 0; d < DHID; ++d) s += Wc[d] * ag[j][d];
        prob[j] = s;
    }
    __syncthreads();
    if (j == 0) {
        float mx = prob[0];
#pragma unroll
        for (int k = 1; k < NCLU; ++k) mx = fmaxf(mx, prob[k]);
        float sum = 0.f;
        float e[NCLU];
#pragma unroll
        for (int k = 0; k < NCLU; ++k) { e[k] = expf(prob[k] - mx); sum += e[k]; }
#pragma unroll
        for (int k = 0; k < NCLU; ++k) prob[k] = e[k] / sum;
    }
    __syncthreads();

    // H = sum_k prob[k] * h_path[k]
    float o = 0.f;
#pragma unroll
    for (int k = 0; k < NCLU; ++k) o += prob[k] * hp[k][j];
    out[j] = o;
}

// ---------------------------------------------------------------
extern "C" void kernel_launch(void* const* d_in, const int* in_sizes, int n_in,
                              void* d_out, int out_size) {
    const float* x    = (const float*)d_in[0];   // [1, 65536, 1024]
    const int*   cid  = (const int*)  d_in[1];   // [65536]
    const float* W1   = (const float*)d_in[2];   // [256, 1024]
    const float* b1   = (const float*)d_in[3];   // [256]
    const float* Wf   = (const float*)d_in[4];
    const float* bf   = (const float*)d_in[5];
    const float* Wa   = (const float*)d_in[6];
    const float* ba   = (const float*)d_in[7];
    const float* Wb   = (const float*)d_in[8];
    const float* bb   = (const float*)d_in[9];
    const float* Wc   = (const float*)d_in[10];
    const float* bc   = (const float*)d_in[11];
    float* out = (float*)d_out;

    prep_kernel<<<512, 512>>>(W1);
    main_kernel<<<512, 512>>>(x, cid, b1);
    finalize_kernel<<<1, 256>>>(Wf, bf, Wa, ba, Wb, bb, Wc, bc, out);
}

// round 8
// speedup vs baseline: 1.0188x; 1.0188x over previous
#include <cuda_runtime.h>
#include <cuda_bf16.h>
#include <cstdint>
#include <math.h>

#define NCLU 8
#define DIN  1024
#define DHID 256
#define NTOK 65536
#define RPB  128            // rows per CTA
#define KT   64             // k per tile
#define NKT  (DIN / KT)     // 16 tiles
#define PADK 72             // padded bf16 row stride (144 B, 16B-aligned)
#define ROWB (PADK * 2)     // 144 bytes per row

// ---- dynamic shared memory layout (byte offsets) ----
#define SM_A0    0                         // 2 x 128 x 144 = 36864
#define SM_B0    36864                     // 2 x 256 x 144 = 73728
#define SM_ACC   110592                    // 8 x 256 x 4   = 8192
#define SM_B1S   118784                    // 256 floats
#define SM_CID   119808                    // 128 ints
#define SM_HIST  120320                    // 8 u32
#define SM_TOTAL 120384

// ------------- device scratch (no allocs allowed) -------------
__device__ __nv_bfloat16 g_w1b[DHID * DIN];
__device__ float         g_segsum[NCLU * DHID];
__device__ unsigned int  g_counts[NCLU];

__device__ __forceinline__ uint32_t pack2(float a, float b) {
    __nv_bfloat162 h = __floats2bfloat162_rn(a, b);
    return *reinterpret_cast<const uint32_t*>(&h);
}

__device__ __forceinline__ uint32_t smem_u32(const void* p) {
    uint32_t a;
    asm("{ .reg .u64 t; cvta.to.shared.u64 t, %1; cvt.u32.u64 %0, t; }"
        : "=r"(a) : "l"(p));
    return a;
}

__device__ __forceinline__ void cp_async16(uint32_t dst, const void* src) {
    asm volatile("cp.async.cg.shared.global [%0], [%1], 16;"
                 :: "r"(dst), "l"(src) : "memory");
}
#define CP_COMMIT() asm volatile("cp.async.commit_group;" ::: "memory")
#define CP_WAIT(n)  asm volatile("cp.async.wait_group %0;" :: "n"(n) : "memory")

__device__ __forceinline__ void mma16816(float c[4], const uint32_t a[4],
                                         uint32_t b0, uint32_t b1) {
    asm volatile(
        "mma.sync.aligned.m16n8k16.row.col.f32.bf16.bf16.f32 "
        "{%0,%1,%2,%3}, {%4,%5,%6,%7}, {%8,%9}, {%0,%1,%2,%3};"
        : "+f"(c[0]), "+f"(c[1]), "+f"(c[2]), "+f"(c[3])
        : "r"(a[0]), "r"(a[1]), "r"(a[2]), "r"(a[3]), "r"(b0), "r"(b1));
}

// ---------------------------------------------------------------
// Kernel 1: W1 fp32 -> bf16 (vectorized), zero accumulators
// ---------------------------------------------------------------
__global__ void prep_kernel(const float* __restrict__ W1) {
    int i = blockIdx.x * blockDim.x + threadIdx.x;   // 65536 float4s
    float4 v = reinterpret_cast<const float4*>(W1)[i];
    uint2 o;
    o.x = pack2(v.x, v.y);
    o.y = pack2(v.z, v.w);
    reinterpret_cast<uint2*>(g_w1b)[i] = o;
    if (i < NCLU * DHID) g_segsum[i] = 0.f;
    if (i < NCLU)        g_counts[i] = 0u;
}

// ---------------------------------------------------------------
// Kernel 2: pipelined mma.sync GEMM (128x256x1024 per CTA) +
//           bias + ReLU + per-cluster segment sum.
//   grid 512, block 512 (16 warps, 4x4 warp grid, warp tile 32x64)
// ---------------------------------------------------------------
__global__ void __launch_bounds__(512, 1)
main_kernel(const float* __restrict__ x,
            const int*   __restrict__ cid_g,
            const float* __restrict__ b1_g) {
    extern __shared__ __align__(16) char smem[];

    char* Abuf = smem + SM_A0;     // [2][128][PADK] bf16
    char* Bbuf = smem + SM_B0;     // [2][256][PADK] bf16
    float*        accS  = reinterpret_cast<float*>(smem + SM_ACC);
    float*        b1s   = reinterpret_cast<float*>(smem + SM_B1S);
    int*          cids  = reinterpret_cast<int*>(smem + SM_CID);
    unsigned int* histS = reinterpret_cast<unsigned int*>(smem + SM_HIST);

    const int tid   = threadIdx.x;
    const int lane  = tid & 31;
    const int wid   = tid >> 5;
    const int mBase = (wid >> 2) * 32;       // warp row block
    const int nBase = (wid & 3) * 64;        // warp col block
    const int rowBase = blockIdx.x * RPB;

    // ---- phase 0 ----
    for (int i = tid; i < NCLU * DHID; i += 512) accS[i] = 0.f;
    if (tid < NCLU) histS[tid] = 0u;
    if (tid < DHID) b1s[tid] = b1_g[tid];
    __syncthreads();
    if (tid < RPB) {
        int c = cid_g[rowBase + tid];
        cids[tid] = c;
        atomicAdd(&histS[c], 1u);
    }

    // ---- load-task geometry ----
    // A: 128 rows x 64 k fp32 -> bf16. 1024 chunks of 8 elems; 2 per thread.
    const int a_r0 = tid >> 3,         a_s0 = tid & 7;
    const int a_r1 = (tid + 512) >> 3, a_s1 = (tid + 512) & 7;
    // B: 256 rows x 64 k bf16 = 2048 16B chunks; 4 per thread (cp.async).
    const uint32_t Bsm = smem_u32(Bbuf);

    float4 xa[2][2];
    auto ldgA = [&](int t) {
        const float* xp = x + (size_t)rowBase * DIN + t * KT;
        const float4* p0 = reinterpret_cast<const float4*>(xp + (size_t)a_r0 * DIN + a_s0 * 8);
        xa[0][0] = p0[0];  xa[0][1] = p0[1];
        const float4* p1 = reinterpret_cast<const float4*>(xp + (size_t)a_r1 * DIN + a_s1 * 8);
        xa[1][0] = p1[0];  xa[1][1] = p1[1];
    };
    auto stsA = [&](int b) {
        char* Ab = Abuf + b * (RPB * ROWB);
        uint4 pk;
        pk.x = pack2(xa[0][0].x, xa[0][0].y);
        pk.y = pack2(xa[0][0].z, xa[0][0].w);
        pk.z = pack2(xa[0][1].x, xa[0][1].y);
        pk.w = pack2(xa[0][1].z, xa[0][1].w);
        *reinterpret_cast<uint4*>(Ab + a_r0 * ROWB + a_s0 * 16) = pk;
        pk.x = pack2(xa[1][0].x, xa[1][0].y);
        pk.y = pack2(xa[1][0].z, xa[1][0].w);
        pk.z = pack2(xa[1][1].x, xa[1][1].y);
        pk.w = pack2(xa[1][1].z, xa[1][1].w);
        *reinterpret_cast<uint4*>(Ab + a_r1 * ROWB + a_s1 * 16) = pk;
    };
    auto cpB = [&](int t, int b) {
        uint32_t base = Bsm + b * (DHID * ROWB);
#pragma unroll
        for (int i = 0; i < 4; ++i) {
            int id = tid + i * 512;
            int r = id >> 3, s = id & 7;
            cp_async16(base + r * ROWB + s * 16,
                       g_w1b + (size_t)r * DIN + t * KT + s * 8);
        }
        CP_COMMIT();
    };

    float acc[2][8][4];
#pragma unroll
    for (int m = 0; m < 2; ++m)
#pragma unroll
        for (int n = 0; n < 8; ++n)
#pragma unroll
            for (int q = 0; q < 4; ++q) acc[m][n][q] = 0.f;

    const int fr  = lane >> 2;           // 0..7
    const int fc2 = (lane & 3) << 1;     // 0,2,4,6

    // ---- pipelined mainloop ----
    ldgA(0);
    cpB(0, 0);
    for (int t = 0; t < NKT; ++t) {
        const int b = t & 1;
        stsA(b);                              // buffer b free (compute t-2 synced)
        if (t + 1 < NKT) {
            ldgA(t + 1);                      // overlaps compute below
            cpB(t + 1, b ^ 1);
            CP_WAIT(1);                       // B(t) resident
        } else {
            CP_WAIT(0);
        }
        __syncthreads();

        const __nv_bfloat16* As = reinterpret_cast<const __nv_bfloat16*>(Abuf + b * (RPB * ROWB));
        const __nv_bfloat16* Bs = reinterpret_cast<const __nv_bfloat16*>(Bbuf + b * (DHID * ROWB));

#pragma unroll
        for (int ks = 0; ks < 4; ++ks) {
            const int kb = ks * 16;
            uint32_t a[2][4];
#pragma unroll
            for (int m = 0; m < 2; ++m) {
                const int r = mBase + m * 16 + fr;
                const int c = fc2 + kb;
                a[m][0] = *reinterpret_cast<const uint32_t*>(&As[r * PADK + c]);
                a[m][1] = *reinterpret_cast<const uint32_t*>(&As[(r + 8) * PADK + c]);
                a[m][2] = *reinterpret_cast<const uint32_t*>(&As[r * PADK + c + 8]);
                a[m][3] = *reinterpret_cast<const uint32_t*>(&As[(r + 8) * PADK + c + 8]);
            }
#pragma unroll
            for (int n = 0; n < 8; ++n) {
                const int col = nBase + n * 8 + fr;
                const int kk  = fc2 + kb;
                uint32_t b0 = *reinterpret_cast<const uint32_t*>(&Bs[col * PADK + kk]);
                uint32_t b1 = *reinterpret_cast<const uint32_t*>(&Bs[col * PADK + kk + 8]);
                mma16816(acc[0][n], a[0], b0, b1);
                mma16816(acc[1][n], a[1], b0, b1);
            }
        }
        __syncthreads();                      // buffer b reusable at t+2
    }

    // ---- epilogue: bias + ReLU + per-cluster accumulation ----
#pragma unroll
    for (int m = 0; m < 2; ++m) {
        const int r    = mBase + m * 16 + fr;
        const int cid0 = cids[r];
        const int cid1 = cids[r + 8];
#pragma unroll
        for (int n = 0; n < 8; ++n) {
            const int col = nBase + n * 8 + fc2;
            const float bia0 = b1s[col], bia1 = b1s[col + 1];
            float v00 = fmaxf(acc[m][n][0] + bia0, 0.f);
            float v01 = fmaxf(acc[m][n][1] + bia1, 0.f);
            float v10 = fmaxf(acc[m][n][2] + bia0, 0.f);
            float v11 = fmaxf(acc[m][n][3] + bia1, 0.f);
            atomicAdd(&accS[cid0 * DHID + col],     v00);
            atomicAdd(&accS[cid0 * DHID + col + 1], v01);
            atomicAdd(&accS[cid1 * DHID + col],     v10);
            atomicAdd(&accS[cid1 * DHID + col + 1], v11);
        }
    }
    __syncthreads();

    for (int i = tid; i < NCLU * DHID; i += 512)
        atomicAdd(&g_segsum[i], accS[i]);
    if (tid < NCLU) atomicAdd(&g_counts[tid], histS[tid]);
}

// ---------------------------------------------------------------
// Kernel 3: cluster means + gated attention + softmax + combine
// ---------------------------------------------------------------
__global__ void __launch_bounds__(256, 1)
finalize_kernel(const float* __restrict__ Wf, const float* __restrict__ bf,
                const float* __restrict__ Wa, const float* __restrict__ ba,
                const float* __restrict__ Wb, const float* __restrict__ bb,
                const float* __restrict__ Wc, const float* __restrict__ bc,
                float* __restrict__ out) {
    __shared__ float hc[NCLU][DHID];
    __shared__ float hp[NCLU][DHID];
    __shared__ float ag[NCLU][DHID];
    __shared__ float prob[NCLU];

    const int j = threadIdx.x;

#pragma unroll
    for (int k = 0; k < NCLU; ++k) {
        float cnt = fmaxf((float)g_counts[k], 1.0f);
        hc[k][j] = g_segsum[k * DHID + j] / cnt;
    }
    __syncthreads();

    {   // h_path = relu(hc @ Wf^T + bf)
        float acc[NCLU];
        float bias = bf[j];
#pragma unroll
        for (int k = 0; k < NCLU; ++k) acc[k] = bias;
#pragma unroll 4
        for (int d = 0; d < DHID; ++d) {
            float wv = Wf[j * DHID + d];
#pragma unroll
            for (int k = 0; k < NCLU; ++k) acc[k] += wv * hc[k][d];
        }
#pragma unroll
        for (int k = 0; k < NCLU; ++k) hp[k][j] = fmaxf(acc[k], 0.f);
    }
    __syncthreads();

    {   // a = tanh(hp@Wa^T+ba), g = sigmoid(hp@Wb^T+bb), ag = a*g
        float accA[NCLU], accB[NCLU];
        float biasA = ba[j], biasB = bb[j];
#pragma unroll
        for (int k = 0; k < NCLU; ++k) { accA[k] = biasA; accB[k] = biasB; }
#pragma unroll 4
        for (int d = 0; d < DHID; ++d) {
            float wa = Wa[j * DHID + d];
            float wb = Wb[j * DHID + d];
#pragma unroll
            for (int k = 0; k < NCLU; ++k) {
                float h = hp[k][d];
                accA[k] += wa * h;
                accB[k] += wb * h;
            }
        }
#pragma unroll
        for (int k = 0; k < NCLU; ++k) {
            float a = tanhf(accA[k]);
            float g = 1.0f / (1.0f + expf(-accB[k]));
            ag[k][j] = a * g;
        }
    }
    __syncthreads();

    if (j < NCLU) {
        float s = bc[0];
#pragma unroll 4
        for (int d = 0; d < DHID; ++d) s += Wc[d] * ag[j][d];
        prob[j] = s;
    }
    __syncthreads();
    if (j == 0) {
        float mx = prob[0];
#pragma unroll
        for (int k = 1; k < NCLU; ++k) mx = fmaxf(mx, prob[k]);
        float sum = 0.f, e[NCLU];
#pragma unroll
        for (int k = 0; k < NCLU; ++k) { e[k] = expf(prob[k] - mx); sum += e[k]; }
#pragma unroll
        for (int k = 0; k < NCLU; ++k) prob[k] = e[k] / sum;
    }
    __syncthreads();

    float o = 0.f;
#pragma unroll
    for (int k = 0; k < NCLU; ++k) o += prob[k] * hp[k][j];
    out[j] = o;
}

// ---------------------------------------------------------------
extern "C" void kernel_launch(void* const* d_in, const int* in_sizes, int n_in,
                              void* d_out, int out_size) {
    const float* x   = (const float*)d_in[0];
    const int*   cid = (const int*)  d_in[1];
    const float* W1  = (const float*)d_in[2];
    const float* b1  = (const float*)d_in[3];
    const float* Wf  = (const float*)d_in[4];
    const float* bf  = (const float*)d_in[5];
    const float* Wa  = (const float*)d_in[6];
    const float* ba  = (const float*)d_in[7];
    const float* Wb  = (const float*)d_in[8];
    const float* bb  = (const float*)d_in[9];
    const float* Wc  = (const float*)d_in[10];
    const float* bc  = (const float*)d_in[11];
    float* out = (float*)d_out;

    cudaFuncSetAttribute(main_kernel,
                         cudaFuncAttributeMaxDynamicSharedMemorySize, SM_TOTAL);

    prep_kernel<<<256, 256>>>(W1);
    main_kernel<<<512, 512, SM_TOTAL>>>(x, cid, b1);
    finalize_kernel<<<1, 256>>>(Wf, bf, Wa, ba, Wb, bb, Wc, bc, out);
}

// round 10
// speedup vs baseline: 1.1247x; 1.1040x over previous
#include <cuda_runtime.h>
#include <cuda_bf16.h>
#include <cstdint>
#include <math.h>

#define NCLU 8
#define DIN  1024
#define DHID 256
#define NTOK 65536
#define RPB  64             // rows per CTA
#define KT   64             // k per tile
#define NKT  (DIN / KT)     // 16 tiles
#define PADK 72             // padded bf16 row stride (144 B, 16B-aligned)
#define ROWB (PADK * 2)     // 144 bytes per row

// ---- dynamic shared memory layout (byte offsets) ----
#define SM_A0    0                         // 2 x 64 x 144  = 18432
#define SM_B0    18432                     // 2 x 256 x 144 = 73728
#define SM_ACC   92160                     // 8 x 256 x 4   = 8192
#define SM_B1S   100352                    // 256 floats
#define SM_CID   101376                    // 64 ints
#define SM_HIST  101632                    // 8 u32
#define SM_TOTAL 101664

// ------------- device scratch (no allocs allowed) -------------
__device__ __nv_bfloat16 g_w1b[DHID * DIN];
__device__ float         g_segsum[NCLU * DHID];
__device__ unsigned int  g_counts[NCLU];

__device__ __forceinline__ uint32_t pack2(float a, float b) {
    __nv_bfloat162 h = __floats2bfloat162_rn(a, b);
    return *reinterpret_cast<const uint32_t*>(&h);
}

__device__ __forceinline__ uint32_t smem_u32(const void* p) {
    uint32_t a;
    asm("{ .reg .u64 t; cvta.to.shared.u64 t, %1; cvt.u32.u64 %0, t; }"
        : "=r"(a) : "l"(p));
    return a;
}

__device__ __forceinline__ void cp_async16(uint32_t dst, const void* src) {
    asm volatile("cp.async.cg.shared.global [%0], [%1], 16;"
                 :: "r"(dst), "l"(src) : "memory");
}
#define CP_COMMIT() asm volatile("cp.async.commit_group;" ::: "memory")
#define CP_WAIT(n)  asm volatile("cp.async.wait_group %0;" :: "n"(n) : "memory")

__device__ __forceinline__ void mma16816(float c[4], const uint32_t a[4],
                                         uint32_t b0, uint32_t b1) {
    asm volatile(
        "mma.sync.aligned.m16n8k16.row.col.f32.bf16.bf16.f32 "
        "{%0,%1,%2,%3}, {%4,%5,%6,%7}, {%8,%9}, {%0,%1,%2,%3};"
        : "+f"(c[0]), "+f"(c[1]), "+f"(c[2]), "+f"(c[3])
        : "r"(a[0]), "r"(a[1]), "r"(a[2]), "r"(a[3]), "r"(b0), "r"(b1));
}

// ---------------------------------------------------------------
// Kernel 1: W1 fp32 -> bf16 (vectorized), zero accumulators
// ---------------------------------------------------------------
__global__ void prep_kernel(const float* __restrict__ W1) {
    int i = blockIdx.x * blockDim.x + threadIdx.x;   // 65536 float4s
    float4 v = reinterpret_cast<const float4*>(W1)[i];
    uint2 o;
    o.x = pack2(v.x, v.y);
    o.y = pack2(v.z, v.w);
    reinterpret_cast<uint2*>(g_w1b)[i] = o;
    if (i < NCLU * DHID) g_segsum[i] = 0.f;
    if (i < NCLU)        g_counts[i] = 0u;
}

// ---------------------------------------------------------------
// Kernel 2: pipelined mma.sync GEMM (64x256x1024 per CTA) +
//           bias + ReLU + per-cluster segment sum.
//   grid 1024, block 256 (8 warps, 2x4 warp grid, warp tile 32x64)
//   2 CTAs per SM.  Loop structure identical to the passing R7
//   kernel; only tile size / occupancy changed.
// ---------------------------------------------------------------
__global__ void __launch_bounds__(256, 2)
main_kernel(const float* __restrict__ x,
            const int*   __restrict__ cid_g,
            const float* __restrict__ b1_g) {
    extern __shared__ __align__(16) char smem[];

    char* Abuf = smem + SM_A0;     // [2][64][PADK] bf16
    char* Bbuf = smem + SM_B0;     // [2][256][PADK] bf16
    float*        accS  = reinterpret_cast<float*>(smem + SM_ACC);
    float*        b1s   = reinterpret_cast<float*>(smem + SM_B1S);
    int*          cids  = reinterpret_cast<int*>(smem + SM_CID);
    unsigned int* histS = reinterpret_cast<unsigned int*>(smem + SM_HIST);

    const int tid   = threadIdx.x;
    const int lane  = tid & 31;
    const int wid   = tid >> 5;
    const int mBase = (wid >> 2) * 32;       // 0 or 32
    const int nBase = (wid & 3) * 64;        // 0/64/128/192
    const int rowBase = blockIdx.x * RPB;

    // ---- phase 0 ----
    for (int i = tid; i < NCLU * DHID; i += 256) accS[i] = 0.f;
    if (tid < NCLU) histS[tid] = 0u;
    if (tid < DHID) b1s[tid] = b1_g[tid];
    __syncthreads();
    if (tid < RPB) {
        int c = cid_g[rowBase + tid];
        cids[tid] = c;
        atomicAdd(&histS[c], 1u);
    }

    // ---- load-task geometry ----
    // A: 64 rows x 64 k fp32 -> bf16. 512 chunks of 8 floats; 2 per thread.
    const int a_r0 = tid >> 3,         a_s0 = tid & 7;
    const int a_r1 = (tid + 256) >> 3, a_s1 = (tid + 256) & 7;
    // B: 256 rows x 64 k bf16 = 2048 16B chunks; 8 per thread (cp.async).
    const uint32_t Bsm = smem_u32(Bbuf);

    float4 xa[2][2];
    auto ldgA = [&](int t) {
        const float* xp = x + (size_t)rowBase * DIN + t * KT;
        const float4* p0 = reinterpret_cast<const float4*>(xp + (size_t)a_r0 * DIN + a_s0 * 8);
        xa[0][0] = p0[0];  xa[0][1] = p0[1];
        const float4* p1 = reinterpret_cast<const float4*>(xp + (size_t)a_r1 * DIN + a_s1 * 8);
        xa[1][0] = p1[0];  xa[1][1] = p1[1];
    };
    auto stsA = [&](int b) {
        char* Ab = Abuf + b * (RPB * ROWB);
        uint4 pk;
        pk.x = pack2(xa[0][0].x, xa[0][0].y);
        pk.y = pack2(xa[0][0].z, xa[0][0].w);
        pk.z = pack2(xa[0][1].x, xa[0][1].y);
        pk.w = pack2(xa[0][1].z, xa[0][1].w);
        *reinterpret_cast<uint4*>(Ab + a_r0 * ROWB + a_s0 * 16) = pk;
        pk.x = pack2(xa[1][0].x, xa[1][0].y);
        pk.y = pack2(xa[1][0].z, xa[1][0].w);
        pk.z = pack2(xa[1][1].x, xa[1][1].y);
        pk.w = pack2(xa[1][1].z, xa[1][1].w);
        *reinterpret_cast<uint4*>(Ab + a_r1 * ROWB + a_s1 * 16) = pk;
    };
    auto cpB = [&](int t, int b) {
        uint32_t base = Bsm + b * (DHID * ROWB);
#pragma unroll
        for (int i = 0; i < 8; ++i) {
            int id = tid + i * 256;
            int r = id >> 3, s = id & 7;
            cp_async16(base + r * ROWB + s * 16,
                       g_w1b + (size_t)r * DIN + t * KT + s * 8);
        }
        CP_COMMIT();
    };

    float acc[2][8][4];
#pragma unroll
    for (int m = 0; m < 2; ++m)
#pragma unroll
        for (int n = 0; n < 8; ++n)
#pragma unroll
            for (int q = 0; q < 4; ++q) acc[m][n][q] = 0.f;

    const int fr  = lane >> 2;           // 0..7
    const int fc2 = (lane & 3) << 1;     // 0,2,4,6

    // ---- pipelined mainloop (R7-proven structure) ----
    ldgA(0);
    cpB(0, 0);
    for (int t = 0; t < NKT; ++t) {
        const int b = t & 1;
        stsA(b);                              // buffer b free (compute t-2 synced)
        if (t + 1 < NKT) {
            ldgA(t + 1);                      // overlaps compute below
            cpB(t + 1, b ^ 1);
            CP_WAIT(1);                       // B(t) resident
        } else {
            CP_WAIT(0);
        }
        __syncthreads();

        const __nv_bfloat16* As = reinterpret_cast<const __nv_bfloat16*>(Abuf + b * (RPB * ROWB));
        const __nv_bfloat16* Bs = reinterpret_cast<const __nv_bfloat16*>(Bbuf + b * (DHID * ROWB));

#pragma unroll
        for (int ks = 0; ks < 4; ++ks) {
            const int kb = ks * 16;
            uint32_t a[2][4];
#pragma unroll
            for (int m = 0; m < 2; ++m) {
                const int r = mBase + m * 16 + fr;
                const int c = fc2 + kb;
                a[m][0] = *reinterpret_cast<const uint32_t*>(&As[r * PADK + c]);
                a[m][1] = *reinterpret_cast<const uint32_t*>(&As[(r + 8) * PADK + c]);
                a[m][2] = *reinterpret_cast<const uint32_t*>(&As[r * PADK + c + 8]);
                a[m][3] = *reinterpret_cast<const uint32_t*>(&As[(r + 8) * PADK + c + 8]);
            }
#pragma unroll
            for (int n = 0; n < 8; ++n) {
                const int col = nBase + n * 8 + fr;
                const int kk  = fc2 + kb;
                uint32_t b0 = *reinterpret_cast<const uint32_t*>(&Bs[col * PADK + kk]);
                uint32_t b1 = *reinterpret_cast<const uint32_t*>(&Bs[col * PADK + kk + 8]);
                mma16816(acc[0][n], a[0], b0, b1);
                mma16816(acc[1][n], a[1], b0, b1);
            }
        }
        __syncthreads();                      // buffer b reusable at t+2
    }

    // ---- epilogue: bias + ReLU + per-cluster accumulation ----
#pragma unroll
    for (int m = 0; m < 2; ++m) {
        const int r    = mBase + m * 16 + fr;
        const int cid0 = cids[r];
        const int cid1 = cids[r + 8];
#pragma unroll
        for (int n = 0; n < 8; ++n) {
            const int col = nBase + n * 8 + fc2;
            const float bia0 = b1s[col], bia1 = b1s[col + 1];
            float v00 = fmaxf(acc[m][n][0] + bia0, 0.f);
            float v01 = fmaxf(acc[m][n][1] + bia1, 0.f);
            float v10 = fmaxf(acc[m][n][2] + bia0, 0.f);
            float v11 = fmaxf(acc[m][n][3] + bia1, 0.f);
            atomicAdd(&accS[cid0 * DHID + col],     v00);
            atomicAdd(&accS[cid0 * DHID + col + 1], v01);
            atomicAdd(&accS[cid1 * DHID + col],     v10);
            atomicAdd(&accS[cid1 * DHID + col + 1], v11);
        }
    }
    __syncthreads();

    for (int i = tid; i < NCLU * DHID; i += 256)
        atomicAdd(&g_segsum[i], accS[i]);
    if (tid < NCLU) atomicAdd(&g_counts[tid], histS[tid]);
}

// ---------------------------------------------------------------
// Kernel 3: cluster means + gated attention + softmax + combine
// ---------------------------------------------------------------
__global__ void __launch_bounds__(256, 1)
finalize_kernel(const float* __restrict__ Wf, const float* __restrict__ bf,
                const float* __restrict__ Wa, const float* __restrict__ ba,
                const float* __restrict__ Wb, const float* __restrict__ bb,
                const float* __restrict__ Wc, const float* __restrict__ bc,
                float* __restrict__ out) {
    __shared__ float hc[NCLU][DHID];
    __shared__ float hp[NCLU][DHID];
    __shared__ float ag[NCLU][DHID];
    __shared__ float prob[NCLU];

    const int j = threadIdx.x;

#pragma unroll
    for (int k = 0; k < NCLU; ++k) {
        float cnt = fmaxf((float)g_counts[k], 1.0f);
        hc[k][j] = g_segsum[k * DHID + j] / cnt;
    }
    __syncthreads();

    {   // h_path = relu(hc @ Wf^T + bf)
        float acc[NCLU];
        float bias = bf[j];
#pragma unroll
        for (int k = 0; k < NCLU; ++k) acc[k] = bias;
#pragma unroll 4
        for (int d = 0; d < DHID; ++d) {
            float wv = Wf[j * DHID + d];
#pragma unroll
            for (int k = 0; k < NCLU; ++k) acc[k] += wv * hc[k][d];
        }
#pragma unroll
        for (int k = 0; k < NCLU; ++k) hp[k][j] = fmaxf(acc[k], 0.f);
    }
    __syncthreads();

    {   // a = tanh(hp@Wa^T+ba), g = sigmoid(hp@Wb^T+bb), ag = a*g
        float accA[NCLU], accB[NCLU];
        float biasA = ba[j], biasB = bb[j];
#pragma unroll
        for (int k = 0; k < NCLU; ++k) { accA[k] = biasA; accB[k] = biasB; }
#pragma unroll 4
        for (int d = 0; d < DHID; ++d) {
            float wa = Wa[j * DHID + d];
            float wb = Wb[j * DHID + d];
#pragma unroll
            for (int k = 0; k < NCLU; ++k) {
                float h = hp[k][d];
                accA[k] += wa * h;
                accB[k] += wb * h;
            }
        }
#pragma unroll
        for (int k = 0; k < NCLU; ++k) {
            float a = tanhf(accA[k]);
            float g = 1.0f / (1.0f + expf(-accB[k]));
            ag[k][j] = a * g;
        }
    }
    __syncthreads();

    if (j < NCLU) {
        float s = bc[0];
#pragma unroll 4
        for (int d = 0; d < DHID; ++d) s += Wc[d] * ag[j][d];
        prob[j] = s;
    }
    __syncthreads();
    if (j == 0) {
        float mx = prob[0];
#pragma unroll
        for (int k = 1; k < NCLU; ++k) mx = fmaxf(mx, prob[k]);
        float sum = 0.f, e[NCLU];
#pragma unroll
        for (int k = 0; k < NCLU; ++k) { e[k] = expf(prob[k] - mx); sum += e[k]; }
#pragma unroll
        for (int k = 0; k < NCLU; ++k) prob[k] = e[k] / sum;
    }
    __syncthreads();

    float o = 0.f;
#pragma unroll
    for (int k = 0; k < NCLU; ++k) o += prob[k] * hp[k][j];
    out[j] = o;
}

// ---------------------------------------------------------------
extern "C" void kernel_launch(void* const* d_in, const int* in_sizes, int n_in,
                              void* d_out, int out_size) {
    const float* x   = (const float*)d_in[0];
    const int*   cid = (const int*)  d_in[1];
    const float* W1  = (const float*)d_in[2];
    const float* b1  = (const float*)d_in[3];
    const float* Wf  = (const float*)d_in[4];
    const float* bf  = (const float*)d_in[5];
    const float* Wa  = (const float*)d_in[6];
    const float* ba  = (const float*)d_in[7];
    const float* Wb  = (const float*)d_in[8];
    const float* bb  = (const float*)d_in[9];
    const float* Wc  = (const float*)d_in[10];
    const float* bc  = (const float*)d_in[11];
    float* out = (float*)d_out;

    cudaFuncSetAttribute(main_kernel,
                         cudaFuncAttributeMaxDynamicSharedMemorySize, SM_TOTAL);

    prep_kernel<<<256, 256>>>(W1);
    main_kernel<<<1024, 256, SM_TOTAL>>>(x, cid, b1);
    finalize_kernel<<<1, 256>>>(Wf, bf, Wa, ba, Wb, bb, Wc, bc, out);
}